// round 4
// baseline (speedup 1.0000x reference)
#include <cuda_runtime.h>
#include <cuda_bf16.h>

#define B_   2
#define S_   2048
#define D_   1024
#define H_   16
#define DK_  64
#define BS_  (B_*S_)            // 4096
#define NBH_ (B_*H_)            // 32

// ---------------- device scratch (no allocations allowed) -------------------
__device__ __nv_bfloat16 g_xh[BS_ * D_],  g_xl[BS_ * D_];       // x split
__device__ __nv_bfloat16 g_w3h[3 * D_ * D_], g_w3l[3 * D_ * D_]; // wq|wk|wv
__device__ __nv_bfloat16 g_woh[D_ * D_], g_wol[D_ * D_];
__device__ __nv_bfloat16 g_qh[NBH_ * S_ * DK_], g_ql[NBH_ * S_ * DK_];
__device__ __nv_bfloat16 g_kh[NBH_ * S_ * DK_], g_kl[NBH_ * S_ * DK_];
__device__ __nv_bfloat16 g_vth[NBH_ * DK_ * S_], g_vtl[NBH_ * DK_ * S_]; // V^T [bh][d][s]
__device__ __nv_bfloat16 g_ch[BS_ * D_], g_cl[BS_ * D_];        // ctx split
__device__ float g_rsum_part[64][NBH_ * S_];                    // softmax partial sums
__device__ float g_attn_fb[(size_t)NBH_ * S_ * S_];             // fallback

// ---------------- smem layout (per stage) ------------------------------
#define OFF_AH 0
#define OFF_AL 16384
#define OFF_BH 32768
#define OFF_BL 40960
#define STAGE_BYTES 49152

// ---------------- helpers ---------------------------------------------------
__device__ __forceinline__ unsigned smem_u32(const void* p) {
    return (unsigned)__cvta_generic_to_shared(p);
}

__device__ __forceinline__ void ldsm4(unsigned r[4], unsigned addr) {
    asm volatile("ldmatrix.sync.aligned.m8n8.x4.shared.b16 {%0,%1,%2,%3}, [%4];\n"
                 : "=r"(r[0]), "=r"(r[1]), "=r"(r[2]), "=r"(r[3]) : "r"(addr));
}

__device__ __forceinline__ void mma16816(float (&d)[4], const unsigned a[4],
                                         unsigned b0, unsigned b1) {
    asm volatile(
        "mma.sync.aligned.m16n8k16.row.col.f32.bf16.bf16.f32 "
        "{%0,%1,%2,%3}, {%4,%5,%6,%7}, {%8,%9}, {%0,%1,%2,%3};\n"
        : "+f"(d[0]), "+f"(d[1]), "+f"(d[2]), "+f"(d[3])
        : "r"(a[0]), "r"(a[1]), "r"(a[2]), "r"(a[3]), "r"(b0), "r"(b1));
}

// split two floats into packed hi/lo bf16x2
__device__ __forceinline__ void split2(float x, float y, unsigned &h, unsigned &l) {
    __nv_bfloat162 hv = __floats2bfloat162_rn(x, y);
    float rx = x - __low2float(hv);
    float ry = y - __high2float(hv);
    __nv_bfloat162 lv = __floats2bfloat162_rn(rx, ry);
    h = *reinterpret_cast<unsigned*>(&hv);
    l = *reinterpret_cast<unsigned*>(&lv);
}

// swizzled smem byte offset: row stride 128B, 16B chunks XOR'd by row&7
__device__ __forceinline__ unsigned swz(int row, int kb) {
    return (unsigned)(row * 128 + (kb ^ ((row & 7) << 4)));
}

// ---------------- staging ----------------------------------------------------
__device__ __forceinline__ void loadA_bf16(uint4 rh[4], uint4 rl[4],
    const __nv_bfloat16* __restrict__ Ah, const __nv_bfloat16* __restrict__ Al,
    int ld, int m0, int k0, int tid)
{
#pragma unroll
    for (int j = 0; j < 4; j++) {
        int id = tid + j * 256, row = id >> 3, c = id & 7;
        size_t g = (size_t)(m0 + row) * ld + k0 + c * 8;
        rh[j] = *reinterpret_cast<const uint4*>(Ah + g);
        rl[j] = *reinterpret_cast<const uint4*>(Al + g);
    }
}
__device__ __forceinline__ void storeA(char* base, const uint4 rh[4], const uint4 rl[4], int tid)
{
#pragma unroll
    for (int j = 0; j < 4; j++) {
        int id = tid + j * 256, row = id >> 3, c = id & 7;
        unsigned off = swz(row, c * 16);
        *reinterpret_cast<uint4*>(base + OFF_AH + off) = rh[j];
        *reinterpret_cast<uint4*>(base + OFF_AL + off) = rl[j];
    }
}
__device__ __forceinline__ void loadB_bf16(uint4 rh[2], uint4 rl[2],
    const __nv_bfloat16* __restrict__ Bh, const __nv_bfloat16* __restrict__ Bl,
    int ld, int n0, int k0, int tid)
{
#pragma unroll
    for (int j = 0; j < 2; j++) {
        int id = tid + j * 256, row = id >> 3, c = id & 7;
        size_t g = (size_t)(n0 + row) * ld + k0 + c * 8;
        rh[j] = *reinterpret_cast<const uint4*>(Bh + g);
        rl[j] = *reinterpret_cast<const uint4*>(Bl + g);
    }
}
__device__ __forceinline__ void storeB(char* base, const uint4 rh[2], const uint4 rl[2], int tid)
{
#pragma unroll
    for (int j = 0; j < 2; j++) {
        int id = tid + j * 256, row = id >> 3, c = id & 7;
        unsigned off = swz(row, c * 16);
        *reinterpret_cast<uint4*>(base + OFF_BH + off) = rh[j];
        *reinterpret_cast<uint4*>(base + OFF_BL + off) = rl[j];
    }
}
// pv A staging: load exp-scores, normalize, WRITE BACK normalized, keep in regs
__device__ __forceinline__ void loadA_norm(float4 rf[8], float* A,
    int m0, int k0, int tid, const float* s_inv)
{
#pragma unroll
    for (int j = 0; j < 4; j++) {
        int id = tid + j * 256, row = id >> 3, c = id & 7;
        const float inv = s_inv[row];
        float4* p = (float4*)(A + (size_t)(m0 + row) * S_ + k0 + c * 8);
        float4 f0 = p[0], f1 = p[1];
        f0.x *= inv; f0.y *= inv; f0.z *= inv; f0.w *= inv;
        f1.x *= inv; f1.y *= inv; f1.z *= inv; f1.w *= inv;
        p[0] = f0; p[1] = f1;               // normalized attn written back
        rf[2 * j]     = f0;
        rf[2 * j + 1] = f1;
    }
}
// fp32 A staging — split+store
__device__ __forceinline__ void storeA_f32(char* base, const float4 rf[8], int tid)
{
#pragma unroll
    for (int j = 0; j < 4; j++) {
        int id = tid + j * 256, row = id >> 3, c = id & 7;
        const float4 f0 = rf[2 * j], f1 = rf[2 * j + 1];
        uint4 hi, lo;
        split2(f0.x, f0.y, hi.x, lo.x);
        split2(f0.z, f0.w, hi.y, lo.y);
        split2(f1.x, f1.y, hi.z, lo.z);
        split2(f1.z, f1.w, hi.w, lo.w);
        unsigned off = swz(row, c * 16);
        *reinterpret_cast<uint4*>(base + OFF_AH + off) = hi;
        *reinterpret_cast<uint4*>(base + OFF_AL + off) = lo;
    }
}

// ---------------- core compute over one BK=64 stage -------------------------
__device__ __forceinline__ void compute_stage(const char* base, int wm, int wn,
                                              int lane, float acc[2][4][4])
{
    unsigned sb = smem_u32(base);
    const int arow0 = wm * 32 + (lane & 15);
    const int akh   = ((lane >> 4) & 1) * 16;
    const int brow0 = wn * 32 + ((lane >> 4) & 1) * 8 + (lane & 7);
    const int bkh   = ((lane >> 3) & 1) * 16;
#pragma unroll
    for (int ks = 0; ks < 4; ks++) {
        unsigned ah[2][4], al[2][4], bh[2][4], bl[2][4];
#pragma unroll
        for (int mt = 0; mt < 2; mt++) {
            unsigned off = swz(arow0 + mt * 16, ks * 32 + akh);
            ldsm4(ah[mt], sb + OFF_AH + off);
            ldsm4(al[mt], sb + OFF_AL + off);
        }
#pragma unroll
        for (int p = 0; p < 2; p++) {
            unsigned off = swz(brow0 + p * 16, ks * 32 + bkh);
            ldsm4(bh[p], sb + OFF_BH + off);
            ldsm4(bl[p], sb + OFF_BL + off);
        }
#pragma unroll
        for (int mt = 0; mt < 2; mt++)
#pragma unroll
            for (int nt = 0; nt < 4; nt++) {
                unsigned b0h = bh[nt >> 1][(nt & 1) * 2], b1h = bh[nt >> 1][(nt & 1) * 2 + 1];
                unsigned b0l = bl[nt >> 1][(nt & 1) * 2], b1l = bl[nt >> 1][(nt & 1) * 2 + 1];
                mma16816(acc[mt][nt], ah[mt], b0h, b1h);
                mma16816(acc[mt][nt], ah[mt], b0l, b1l);
                mma16816(acc[mt][nt], al[mt], b0h, b1h);
            }
    }
}

// ---------------- prep: all fp32 -> hi/lo bf16 splits in one launch ----------
__global__ void prep_kernel(const float* __restrict__ x,
                            const float* __restrict__ wq,
                            const float* __restrict__ wk,
                            const float* __restrict__ wv,
                            const float* __restrict__ wo)
{
    const int bid = blockIdx.x, tid = threadIdx.x;
    const float* src;
    __nv_bfloat16 *hi, *lo;
    int base;
    if (bid < 8192)        { src = x;  hi = g_xh;            lo = g_xl;            base = 0; }
    else if (bid < 10240)  { src = wq; hi = g_w3h;           lo = g_w3l;           base = 8192; }
    else if (bid < 12288)  { src = wk; hi = g_w3h + D_*D_;   lo = g_w3l + D_*D_;   base = 10240; }
    else if (bid < 14336)  { src = wv; hi = g_w3h + 2*D_*D_; lo = g_w3l + 2*D_*D_; base = 12288; }
    else                   { src = wo; hi = g_woh;           lo = g_wol;           base = 14336; }
    int i = ((bid - base) * 256 + tid) * 2;
    unsigned h, l;
    split2(src[i], src[i + 1], h, l);
    *reinterpret_cast<unsigned*>(hi + i) = h;
    *reinterpret_cast<unsigned*>(lo + i) = l;
}

// ---------------- kernel 1: fused QKV projection ----------------------------
// C[M=4096, N=3072] = x @ W3^T + bias ; Q scaled by 1/8; V stored transposed
__global__ __launch_bounds__(256) void qkv_gemm(const float* __restrict__ bq,
                                                const float* __restrict__ bk,
                                                const float* __restrict__ bv)
{
    extern __shared__ char sm[];
    const int m0 = blockIdx.y * 128, n0 = blockIdx.x * 64;
    const int tid = threadIdx.x, lane = tid & 31, wid = tid >> 5;
    const int wm = wid >> 1, wn = wid & 1;

    float acc[2][4][4] = {};
    uint4 rah[4], ral[4], rbh[2], rbl[2];

    loadA_bf16(rah, ral, g_xh, g_xl, D_, m0, 0, tid);
    loadB_bf16(rbh, rbl, g_w3h, g_w3l, D_, n0, 0, tid);
    storeA(sm, rah, ral, tid);
    storeB(sm, rbh, rbl, tid);
    __syncthreads();

    for (int it = 0; it < 16; it++) {
        const int cur = it & 1;
        if (it + 1 < 16) {
            loadA_bf16(rah, ral, g_xh, g_xl, D_, m0, (it + 1) * 64, tid);
            loadB_bf16(rbh, rbl, g_w3h, g_w3l, D_, n0, (it + 1) * 64, tid);
        }
        compute_stage(sm + cur * STAGE_BYTES, wm, wn, lane, acc);
        if (it + 1 < 16) {
            storeA(sm + (1 - cur) * STAGE_BYTES, rah, ral, tid);
            storeB(sm + (1 - cur) * STAGE_BYTES, rbh, rbl, tid);
        }
        __syncthreads();
    }

    const int reg = n0 >> 10;                 // 0=Q,1=K,2=V
    const int h   = (n0 & 1023) >> 6;
    const float* bp = (reg == 0) ? bq : (reg == 1) ? bk : bv;
    __nv_bfloat16* dH = (reg == 0) ? g_qh : g_kh;
    __nv_bfloat16* dL = (reg == 0) ? g_ql : g_kl;
    const float scale = (reg == 0) ? 0.125f : 1.0f;
    const int tm0 = m0 + wm * 32, tn0 = n0 + wn * 32;

#pragma unroll
    for (int mt = 0; mt < 2; mt++)
#pragma unroll
        for (int nt = 0; nt < 4; nt++) {
            const int c  = tn0 + nt * 8 + 2 * (lane & 3);
            const int d  = c & 63;
            const float bias0 = bp[c & 1023], bias1 = bp[(c & 1023) + 1];
#pragma unroll
            for (int half = 0; half < 2; half++) {
                const int m = tm0 + mt * 16 + (lane >> 2) + half * 8;
                const float v0 = (acc[mt][nt][half * 2]     + bias0) * scale;
                const float v1 = (acc[mt][nt][half * 2 + 1] + bias1) * scale;
                const int b = m >> 11, s = m & 2047;
                const size_t bh = (size_t)(b * H_ + h);
                unsigned hh, ll;
                split2(v0, v1, hh, ll);
                if (reg < 2) {
                    size_t idx = (bh * S_ + s) * DK_ + d;
                    *reinterpret_cast<unsigned*>(dH + idx) = hh;
                    *reinterpret_cast<unsigned*>(dL + idx) = ll;
                } else {
                    size_t i0 = (bh * DK_ + d) * S_ + s;
                    __nv_bfloat162 hv = *reinterpret_cast<__nv_bfloat162*>(&hh);
                    __nv_bfloat162 lv = *reinterpret_cast<__nv_bfloat162*>(&ll);
                    g_vth[i0]      = __low2bfloat16(hv);
                    g_vtl[i0]      = __low2bfloat16(lv);
                    g_vth[i0 + S_] = __high2bfloat16(hv);
                    g_vtl[i0 + S_] = __high2bfloat16(lv);
                }
            }
        }
}

// ---------------- kernel 2: scores -> exp(QK^T/8), partial row sums ----------
__global__ __launch_bounds__(256) void scores_gemm(float* __restrict__ attn_arg)
{
    extern __shared__ char sm[];
    float* attn = attn_arg ? attn_arg : g_attn_fb;
    const int bh = blockIdx.z;
    const int m0 = blockIdx.y * 128, n0 = blockIdx.x * 64;
    const int tid = threadIdx.x, lane = tid & 31, wid = tid >> 5;
    const int wm = wid >> 1, wn = wid & 1;

    const __nv_bfloat16* Ah = g_qh + (size_t)bh * S_ * DK_;
    const __nv_bfloat16* Al = g_ql + (size_t)bh * S_ * DK_;
    const __nv_bfloat16* Bh = g_kh + (size_t)bh * S_ * DK_;
    const __nv_bfloat16* Bl = g_kl + (size_t)bh * S_ * DK_;

    float acc[2][4][4] = {};
    uint4 rah[4], ral[4], rbh[2], rbl[2];
    loadA_bf16(rah, ral, Ah, Al, DK_, m0, 0, tid);
    loadB_bf16(rbh, rbl, Bh, Bl, DK_, n0, 0, tid);
    storeA(sm, rah, ral, tid);
    storeB(sm, rbh, rbl, tid);
    __syncthreads();
    compute_stage(sm, wm, wn, lane, acc);

    float* C = attn + (size_t)bh * S_ * S_;
    const int tm0 = m0 + wm * 32, tn0 = n0 + wn * 32;
    float rpart[2][2] = {};
#pragma unroll
    for (int mt = 0; mt < 2; mt++)
#pragma unroll
        for (int nt = 0; nt < 4; nt++) {
            const int c = tn0 + nt * 8 + 2 * (lane & 3);
#pragma unroll
            for (int half = 0; half < 2; half++) {
                const int m = tm0 + mt * 16 + (lane >> 2) + half * 8;
                const float e0 = __expf(acc[mt][nt][half * 2]);
                const float e1 = __expf(acc[mt][nt][half * 2 + 1]);
                float2 v = { e0, e1 };
                *reinterpret_cast<float2*>(C + (size_t)m * S_ + c) = v;
                rpart[mt][half] += e0 + e1;
            }
        }

    // deterministic partial row sums: slot = n-tile*2 + wn (64 slots total)
    const int slot = blockIdx.x * 2 + wn;
#pragma unroll
    for (int mt = 0; mt < 2; mt++)
#pragma unroll
        for (int half = 0; half < 2; half++) {
            float v = rpart[mt][half];
            v += __shfl_xor_sync(0xffffffffu, v, 1);
            v += __shfl_xor_sync(0xffffffffu, v, 2);
            if ((lane & 3) == 0) {
                const int m = tm0 + mt * 16 + (lane >> 2) + half * 8;
                g_rsum_part[slot][(size_t)bh * S_ + m] = v;
            }
        }
}

// ---------------- kernel 3: ctx = softmax(attn) @ V, normalize attn in place -
__global__ __launch_bounds__(256) void pv_gemm(float* __restrict__ attn_arg)
{
    extern __shared__ char sm[];
    __shared__ float s_inv[128];
    float* attn = attn_arg ? attn_arg : g_attn_fb;
    const int bh = blockIdx.z;
    const int m0 = blockIdx.y * 128;
    const int tid = threadIdx.x, lane = tid & 31, wid = tid >> 5;
    const int wm = wid >> 1, wn = wid & 1;

    // row inverse sums from 64 deterministic partials
    if (tid < 128) {
        float s = 0.f;
#pragma unroll
        for (int p = 0; p < 64; p++)
            s += g_rsum_part[p][(size_t)bh * S_ + m0 + tid];
        s_inv[tid] = 1.0f / s;
    }
    __syncthreads();

    float* A = attn + (size_t)bh * S_ * S_;
    const __nv_bfloat16* Bh = g_vth + (size_t)bh * DK_ * S_;
    const __nv_bfloat16* Bl = g_vtl + (size_t)bh * DK_ * S_;

    float acc[2][4][4] = {};
    float4 rf[8];
    uint4 rbh[2], rbl[2];

    loadA_norm(rf, A, m0, 0, tid, s_inv);
    loadB_bf16(rbh, rbl, Bh, Bl, S_, 0, 0, tid);
    storeA_f32(sm, rf, tid);
    storeB(sm, rbh, rbl, tid);
    __syncthreads();

    for (int it = 0; it < 32; it++) {
        const int cur = it & 1;
        if (it + 1 < 32) {
            loadA_norm(rf, A, m0, (it + 1) * 64, tid, s_inv);
            loadB_bf16(rbh, rbl, Bh, Bl, S_, 0, (it + 1) * 64, tid);
        }
        compute_stage(sm + cur * STAGE_BYTES, wm, wn, lane, acc);
        if (it + 1 < 32) {
            storeA_f32(sm + (1 - cur) * STAGE_BYTES, rf, tid);
            storeB(sm + (1 - cur) * STAGE_BYTES, rbh, rbl, tid);
        }
        __syncthreads();
    }

    // epilogue -> ctx hi/lo [b, s, h*64 + d]
    const int b = bh >> 4, h = bh & 15;
    const int tm0 = m0 + wm * 32, tn0 = wn * 32;
#pragma unroll
    for (int mt = 0; mt < 2; mt++)
#pragma unroll
        for (int nt = 0; nt < 4; nt++) {
            const int c = tn0 + nt * 8 + 2 * (lane & 3);
#pragma unroll
            for (int half = 0; half < 2; half++) {
                const int s = tm0 + mt * 16 + (lane >> 2) + half * 8;
                unsigned hh, ll;
                split2(acc[mt][nt][half * 2], acc[mt][nt][half * 2 + 1], hh, ll);
                size_t idx = ((size_t)(b * S_ + s)) * D_ + h * DK_ + c;
                *reinterpret_cast<unsigned*>(g_ch + idx) = hh;
                *reinterpret_cast<unsigned*>(g_cl + idx) = ll;
            }
        }
}

// ---------------- kernel 4: out = ctx @ Wo^T + bo ----------------------------
__global__ __launch_bounds__(256) void oproj_gemm(const float* __restrict__ bo,
                                                  float* __restrict__ out)
{
    extern __shared__ char sm[];
    const int m0 = blockIdx.y * 128, n0 = blockIdx.x * 64;
    const int tid = threadIdx.x, lane = tid & 31, wid = tid >> 5;
    const int wm = wid >> 1, wn = wid & 1;

    float acc[2][4][4] = {};
    uint4 rah[4], ral[4], rbh[2], rbl[2];

    loadA_bf16(rah, ral, g_ch, g_cl, D_, m0, 0, tid);
    loadB_bf16(rbh, rbl, g_woh, g_wol, D_, n0, 0, tid);
    storeA(sm, rah, ral, tid);
    storeB(sm, rbh, rbl, tid);
    __syncthreads();

    for (int it = 0; it < 16; it++) {
        const int cur = it & 1;
        if (it + 1 < 16) {
            loadA_bf16(rah, ral, g_ch, g_cl, D_, m0, (it + 1) * 64, tid);
            loadB_bf16(rbh, rbl, g_woh, g_wol, D_, n0, (it + 1) * 64, tid);
        }
        compute_stage(sm + cur * STAGE_BYTES, wm, wn, lane, acc);
        if (it + 1 < 16) {
            storeA(sm + (1 - cur) * STAGE_BYTES, rah, ral, tid);
            storeB(sm + (1 - cur) * STAGE_BYTES, rbh, rbl, tid);
        }
        __syncthreads();
    }

    const int tm0 = m0 + wm * 32, tn0 = n0 + wn * 32;
#pragma unroll
    for (int mt = 0; mt < 2; mt++)
#pragma unroll
        for (int nt = 0; nt < 4; nt++) {
            const int c = tn0 + nt * 8 + 2 * (lane & 3);
            const float b0 = bo[c], b1 = bo[c + 1];
#pragma unroll
            for (int half = 0; half < 2; half++) {
                const int m = tm0 + mt * 16 + (lane >> 2) + half * 8;
                float2 v = { acc[mt][nt][half * 2] + b0,
                             acc[mt][nt][half * 2 + 1] + b1 };
                *reinterpret_cast<float2*>(out + (size_t)m * D_ + c) = v;
            }
        }
}

// ---------------------------------------------------------------------------
extern "C" void kernel_launch(void* const* d_in, const int* in_sizes, int n_in,
                              void* d_out, int out_size)
{
    const float* x  = (const float*)d_in[0];
    const float* wq = (const float*)d_in[1];
    const float* bq = (const float*)d_in[2];
    const float* wk = (const float*)d_in[3];
    const float* bk = (const float*)d_in[4];
    const float* wv = (const float*)d_in[5];
    const float* bv = (const float*)d_in[6];
    const float* wo = (const float*)d_in[7];
    const float* bo = (const float*)d_in[8];

    float* out = (float*)d_out;
    const long long OUT_E  = (long long)BS_ * D_;
    const long long ATTN_E = (long long)NBH_ * S_ * S_;
    float* attn = ((long long)out_size >= OUT_E + ATTN_E) ? (out + OUT_E) : nullptr;

    static bool attr_done = false;
    if (!attr_done) {
        cudaFuncSetAttribute(qkv_gemm,    cudaFuncAttributeMaxDynamicSharedMemorySize, 2 * STAGE_BYTES);
        cudaFuncSetAttribute(pv_gemm,     cudaFuncAttributeMaxDynamicSharedMemorySize, 2 * STAGE_BYTES);
        cudaFuncSetAttribute(oproj_gemm,  cudaFuncAttributeMaxDynamicSharedMemorySize, 2 * STAGE_BYTES);
        cudaFuncSetAttribute(scores_gemm, cudaFuncAttributeMaxDynamicSharedMemorySize, STAGE_BYTES);
        attr_done = true;
    }

    // 0. precision splits (one launch)
    prep_kernel<<<16384, 256>>>(x, wq, wk, wv, wo);

    // 1. QKV projection (fused N=3072), Q pre-scaled by 1/8
    qkv_gemm<<<dim3(3 * D_ / 64, BS_ / 128), 256, 2 * STAGE_BYTES>>>(bq, bk, bv);

    // 2. scores = exp(QK^T/8) + deterministic partial row sums
    scores_gemm<<<dim3(S_ / 64, S_ / 128, NBH_), 256, STAGE_BYTES>>>(attn);

    // 3. ctx = softmax(attn) @ V ; attn normalized in place
    pv_gemm<<<dim3(1, S_ / 128, NBH_), 256, 2 * STAGE_BYTES>>>(attn);

    // 4. out projection
    oproj_gemm<<<dim3(D_ / 64, BS_ / 128), 256, 2 * STAGE_BYTES>>>(bo, out);
}

// round 5
// speedup vs baseline: 1.5598x; 1.5598x over previous
#include <cuda_runtime.h>
#include <cuda_bf16.h>

#define B_   2
#define S_   2048
#define D_   1024
#define H_   16
#define DK_  64
#define BS_  (B_*S_)            // 4096
#define NBH_ (B_*H_)            // 32

// ---------------- device scratch (no allocations allowed) -------------------
__device__ __nv_bfloat16 g_xh[BS_ * D_],  g_xl[BS_ * D_];
__device__ __nv_bfloat16 g_w3h[3 * D_ * D_], g_w3l[3 * D_ * D_];
__device__ __nv_bfloat16 g_woh[D_ * D_], g_wol[D_ * D_];
__device__ __nv_bfloat16 g_qh[NBH_ * S_ * DK_], g_ql[NBH_ * S_ * DK_];
__device__ __nv_bfloat16 g_kh[NBH_ * S_ * DK_], g_kl[NBH_ * S_ * DK_];
__device__ __nv_bfloat16 g_vth[NBH_ * DK_ * S_], g_vtl[NBH_ * DK_ * S_]; // V^T [bh][d][s]
__device__ __nv_bfloat16 g_ch[BS_ * D_], g_cl[BS_ * D_];
__device__ __nv_bfloat16 g_ph[(size_t)NBH_ * S_ * S_];   // exp(scores) hi
__device__ __nv_bfloat16 g_pl[(size_t)NBH_ * S_ * S_];   // exp(scores) lo
__device__ float g_rsum_part[64][NBH_ * S_];              // deterministic partials
__device__ float g_inv[NBH_ * S_];                        // 1/rowsum
__device__ float g_ctxp[4 * BS_ * D_];                    // split-K ctx partials
__device__ float g_attn_fb[(size_t)NBH_ * S_ * S_];       // fallback

// ---------------- smem layout (per stage) -------------------------------
#define OFF_AH 0
#define OFF_AL 16384
#define OFF_BH 32768
#define OFF_BL 40960
#define STAGE_BYTES 49152

// ---------------- helpers ----------------------------------------------------
__device__ __forceinline__ unsigned smem_u32(const void* p) {
    return (unsigned)__cvta_generic_to_shared(p);
}
__device__ __forceinline__ void ldsm4(unsigned r[4], unsigned addr) {
    asm volatile("ldmatrix.sync.aligned.m8n8.x4.shared.b16 {%0,%1,%2,%3}, [%4];\n"
                 : "=r"(r[0]), "=r"(r[1]), "=r"(r[2]), "=r"(r[3]) : "r"(addr));
}
__device__ __forceinline__ void mma16816(float (&d)[4], const unsigned a[4],
                                         unsigned b0, unsigned b1) {
    asm volatile(
        "mma.sync.aligned.m16n8k16.row.col.f32.bf16.bf16.f32 "
        "{%0,%1,%2,%3}, {%4,%5,%6,%7}, {%8,%9}, {%0,%1,%2,%3};\n"
        : "+f"(d[0]), "+f"(d[1]), "+f"(d[2]), "+f"(d[3])
        : "r"(a[0]), "r"(a[1]), "r"(a[2]), "r"(a[3]), "r"(b0), "r"(b1));
}
__device__ __forceinline__ void split2(float x, float y, unsigned &h, unsigned &l) {
    __nv_bfloat162 hv = __floats2bfloat162_rn(x, y);
    float rx = x - __low2float(hv);
    float ry = y - __high2float(hv);
    __nv_bfloat162 lv = __floats2bfloat162_rn(rx, ry);
    h = *reinterpret_cast<unsigned*>(&hv);
    l = *reinterpret_cast<unsigned*>(&lv);
}
__device__ __forceinline__ unsigned swz(int row, int kb) {
    return (unsigned)(row * 128 + (kb ^ ((row & 7) << 4)));
}
__device__ __forceinline__ void cp16(unsigned dst, const void* src) {
    asm volatile("cp.async.cg.shared.global [%0], [%1], 16;\n" :: "r"(dst), "l"(src));
}
#define CP_COMMIT asm volatile("cp.async.commit_group;\n" ::: "memory")
#define CP_WAIT1  asm volatile("cp.async.wait_group 1;\n" ::: "memory")
#define CP_WAIT0  asm volatile("cp.async.wait_group 0;\n" ::: "memory")

// ---------------- cp.async tile staging ---------------------------------------
__device__ __forceinline__ void cpA_tile(unsigned AH, unsigned AL,
    const __nv_bfloat16* __restrict__ Ah, const __nv_bfloat16* __restrict__ Al,
    int ld, int m0, int k0, int tid)
{
#pragma unroll
    for (int j = 0; j < 4; j++) {
        int id = tid + j * 256, row = id >> 3, c = id & 7;
        size_t g = (size_t)(m0 + row) * ld + k0 + c * 8;
        unsigned o = swz(row, c * 16);
        cp16(AH + o, Ah + g);
        cp16(AL + o, Al + g);
    }
}
__device__ __forceinline__ void cpB_tile(unsigned BH, unsigned BL,
    const __nv_bfloat16* __restrict__ Bh, const __nv_bfloat16* __restrict__ Bl,
    int ld, int n0, int k0, int tid)
{
#pragma unroll
    for (int j = 0; j < 2; j++) {
        int id = tid + j * 256, row = id >> 3, c = id & 7;
        size_t g = (size_t)(n0 + row) * ld + k0 + c * 8;
        unsigned o = swz(row, c * 16);
        cp16(BH + o, Bh + g);
        cp16(BL + o, Bl + g);
    }
}

// ---------------- core compute over one BK=64 stage ---------------------------
__device__ __forceinline__ void compute_stage(unsigned sb, int wm, int wn,
                                              int lane, float acc[2][4][4])
{
    const int arow0 = wm * 32 + (lane & 15);
    const int akh   = ((lane >> 4) & 1) * 16;
    const int brow0 = wn * 32 + ((lane >> 4) & 1) * 8 + (lane & 7);
    const int bkh   = ((lane >> 3) & 1) * 16;
#pragma unroll
    for (int ks = 0; ks < 4; ks++) {
        unsigned ah[2][4], al[2][4], bh[2][4], bl[2][4];
#pragma unroll
        for (int mt = 0; mt < 2; mt++) {
            unsigned off = swz(arow0 + mt * 16, ks * 32 + akh);
            ldsm4(ah[mt], sb + OFF_AH + off);
            ldsm4(al[mt], sb + OFF_AL + off);
        }
#pragma unroll
        for (int p = 0; p < 2; p++) {
            unsigned off = swz(brow0 + p * 16, ks * 32 + bkh);
            ldsm4(bh[p], sb + OFF_BH + off);
            ldsm4(bl[p], sb + OFF_BL + off);
        }
#pragma unroll
        for (int mt = 0; mt < 2; mt++)
#pragma unroll
            for (int nt = 0; nt < 4; nt++) {
                unsigned b0h = bh[nt >> 1][(nt & 1) * 2], b1h = bh[nt >> 1][(nt & 1) * 2 + 1];
                unsigned b0l = bl[nt >> 1][(nt & 1) * 2], b1l = bl[nt >> 1][(nt & 1) * 2 + 1];
                mma16816(acc[mt][nt], ah[mt], b0h, b1h);
                mma16816(acc[mt][nt], ah[mt], b0l, b1l);
                mma16816(acc[mt][nt], al[mt], b0h, b1h);
            }
    }
}

// ---------------- prep: fp32 -> hi/lo bf16 splits ------------------------------
__global__ void prep_kernel(const float* __restrict__ x,
                            const float* __restrict__ wq,
                            const float* __restrict__ wk,
                            const float* __restrict__ wv,
                            const float* __restrict__ wo)
{
    const int bid = blockIdx.x, tid = threadIdx.x;
    const float* src;
    __nv_bfloat16 *hi, *lo;
    int base;
    if (bid < 8192)        { src = x;  hi = g_xh;            lo = g_xl;            base = 0; }
    else if (bid < 10240)  { src = wq; hi = g_w3h;           lo = g_w3l;           base = 8192; }
    else if (bid < 12288)  { src = wk; hi = g_w3h + D_*D_;   lo = g_w3l + D_*D_;   base = 10240; }
    else if (bid < 14336)  { src = wv; hi = g_w3h + 2*D_*D_; lo = g_w3l + 2*D_*D_; base = 12288; }
    else                   { src = wo; hi = g_woh;           lo = g_wol;           base = 14336; }
    int i = ((bid - base) * 256 + tid) * 2;
    unsigned h, l;
    split2(src[i], src[i + 1], h, l);
    *reinterpret_cast<unsigned*>(hi + i) = h;
    *reinterpret_cast<unsigned*>(lo + i) = l;
}

// =============================================================================
// Kernel 1: fused QKV projection; Q pre-scaled by 1/8; V stored transposed
// =============================================================================
__global__ __launch_bounds__(256, 2) void qkv_gemm(const float* __restrict__ bq,
                                                   const float* __restrict__ bk,
                                                   const float* __restrict__ bv)
{
    extern __shared__ char sm[];
    const unsigned sb = smem_u32(sm);
    const int m0 = blockIdx.y * 128, n0 = blockIdx.x * 64;
    const int tid = threadIdx.x, lane = tid & 31, wid = tid >> 5;
    const int wm = wid >> 1, wn = wid & 1;
    float acc[2][4][4] = {};

    cpA_tile(sb + OFF_AH, sb + OFF_AL, g_xh, g_xl, D_, m0, 0, tid);
    cpB_tile(sb + OFF_BH, sb + OFF_BL, g_w3h, g_w3l, D_, n0, 0, tid);
    CP_COMMIT;
    for (int it = 0; it < 16; it++) {
        const unsigned cb = sb + (it & 1) * STAGE_BYTES;
        if (it + 1 < 16) {
            const unsigned nb = sb + ((it + 1) & 1) * STAGE_BYTES;
            cpA_tile(nb + OFF_AH, nb + OFF_AL, g_xh, g_xl, D_, m0, (it + 1) * 64, tid);
            cpB_tile(nb + OFF_BH, nb + OFF_BL, g_w3h, g_w3l, D_, n0, (it + 1) * 64, tid);
            CP_COMMIT;
            CP_WAIT1;
        } else { CP_WAIT0; }
        __syncthreads();
        compute_stage(cb, wm, wn, lane, acc);
        __syncthreads();
    }

    const int reg = n0 >> 10;                 // 0=Q,1=K,2=V
    const int h   = (n0 & 1023) >> 6;
    const float* bp = (reg == 0) ? bq : (reg == 1) ? bk : bv;
    __nv_bfloat16* dH = (reg == 0) ? g_qh : g_kh;
    __nv_bfloat16* dL = (reg == 0) ? g_ql : g_kl;
    const float scale = (reg == 0) ? 0.125f : 1.0f;
    const int tm0 = m0 + wm * 32, tn0 = n0 + wn * 32;

#pragma unroll
    for (int mt = 0; mt < 2; mt++)
#pragma unroll
        for (int nt = 0; nt < 4; nt++) {
            const int c  = tn0 + nt * 8 + 2 * (lane & 3);
            const int d  = c & 63;
            const float bias0 = bp[c & 1023], bias1 = bp[(c & 1023) + 1];
#pragma unroll
            for (int half = 0; half < 2; half++) {
                const int m = tm0 + mt * 16 + (lane >> 2) + half * 8;
                const float v0 = (acc[mt][nt][half * 2]     + bias0) * scale;
                const float v1 = (acc[mt][nt][half * 2 + 1] + bias1) * scale;
                const int b = m >> 11, s = m & 2047;
                const size_t bh = (size_t)(b * H_ + h);
                unsigned hh, ll;
                split2(v0, v1, hh, ll);
                if (reg < 2) {
                    size_t idx = (bh * S_ + s) * DK_ + d;
                    *reinterpret_cast<unsigned*>(dH + idx) = hh;
                    *reinterpret_cast<unsigned*>(dL + idx) = ll;
                } else {
                    size_t i0 = (bh * DK_ + d) * S_ + s;
                    __nv_bfloat162 hv = *reinterpret_cast<__nv_bfloat162*>(&hh);
                    __nv_bfloat162 lv = *reinterpret_cast<__nv_bfloat162*>(&ll);
                    g_vth[i0]      = __low2bfloat16(hv);
                    g_vtl[i0]      = __low2bfloat16(lv);
                    g_vth[i0 + S_] = __high2bfloat16(hv);
                    g_vtl[i0 + S_] = __high2bfloat16(lv);
                }
            }
        }
}

// =============================================================================
// Kernel 2: P = exp(QK^T/8) as bf16 hi/lo + deterministic partial row sums
// =============================================================================
__global__ __launch_bounds__(256) void scores_gemm()
{
    extern __shared__ char sm[];
    const unsigned sb = smem_u32(sm);
    const int bh = blockIdx.z;
    const int m0 = blockIdx.y * 128, n0 = blockIdx.x * 64;
    const int tid = threadIdx.x, lane = tid & 31, wid = tid >> 5;
    const int wm = wid >> 1, wn = wid & 1;

    const __nv_bfloat16* Ah = g_qh + (size_t)bh * S_ * DK_;
    const __nv_bfloat16* Al = g_ql + (size_t)bh * S_ * DK_;
    const __nv_bfloat16* Bh = g_kh + (size_t)bh * S_ * DK_;
    const __nv_bfloat16* Bl = g_kl + (size_t)bh * S_ * DK_;

    float acc[2][4][4] = {};
    cpA_tile(sb + OFF_AH, sb + OFF_AL, Ah, Al, DK_, m0, 0, tid);
    cpB_tile(sb + OFF_BH, sb + OFF_BL, Bh, Bl, DK_, n0, 0, tid);
    CP_COMMIT;
    CP_WAIT0;
    __syncthreads();
    compute_stage(sb, wm, wn, lane, acc);

    __nv_bfloat16* Ph = g_ph + (size_t)bh * S_ * S_;
    __nv_bfloat16* Pl = g_pl + (size_t)bh * S_ * S_;
    const int tm0 = m0 + wm * 32, tn0 = n0 + wn * 32;
    float rpart[2][2] = {};
#pragma unroll
    for (int mt = 0; mt < 2; mt++)
#pragma unroll
        for (int nt = 0; nt < 4; nt++) {
            const int c = tn0 + nt * 8 + 2 * (lane & 3);
#pragma unroll
            for (int half = 0; half < 2; half++) {
                const int m = tm0 + mt * 16 + (lane >> 2) + half * 8;
                const float e0 = __expf(acc[mt][nt][half * 2]);
                const float e1 = __expf(acc[mt][nt][half * 2 + 1]);
                unsigned hh, ll;
                split2(e0, e1, hh, ll);
                size_t idx = (size_t)m * S_ + c;
                *reinterpret_cast<unsigned*>(Ph + idx) = hh;
                *reinterpret_cast<unsigned*>(Pl + idx) = ll;
                rpart[mt][half] += e0 + e1;
            }
        }

    const int slot = blockIdx.x * 2 + wn;
#pragma unroll
    for (int mt = 0; mt < 2; mt++)
#pragma unroll
        for (int half = 0; half < 2; half++) {
            float v = rpart[mt][half];
            v += __shfl_xor_sync(0xffffffffu, v, 1);
            v += __shfl_xor_sync(0xffffffffu, v, 2);
            if ((lane & 3) == 0) {
                const int m = tm0 + mt * 16 + (lane >> 2) + half * 8;
                g_rsum_part[slot][(size_t)bh * S_ + m] = v;
            }
        }
}

// ---------------- inv_kernel: 1/rowsum from 64 partials ------------------------
__global__ void inv_kernel()
{
    const int r = blockIdx.x * 256 + threadIdx.x;   // 65536 rows
    float s = 0.f;
#pragma unroll
    for (int p = 0; p < 64; p++) s += g_rsum_part[p][r];
    g_inv[r] = 1.0f / s;
}

// =============================================================================
// Kernel 3: pv split-K: partial ctx = (P·V)·inv ; also writes normalized attn fp32
// grid (kz=4, mtile=16, bh=32)
// =============================================================================
__global__ __launch_bounds__(256, 2) void pv_gemm(float* __restrict__ attn_arg)
{
    extern __shared__ char sm[];
    __shared__ float s_inv[128];
    const unsigned sb = smem_u32(sm);
    float* attn = attn_arg ? attn_arg : g_attn_fb;
    const int kz = blockIdx.x, bh = blockIdx.z;
    const int m0 = blockIdx.y * 128;
    const int tid = threadIdx.x, lane = tid & 31, wid = tid >> 5;
    const int wm = wid >> 1, wn = wid & 1;

    if (tid < 128) s_inv[tid] = g_inv[(size_t)bh * S_ + m0 + tid];

    const __nv_bfloat16* Ph = g_ph + (size_t)bh * S_ * S_;
    const __nv_bfloat16* Pl = g_pl + (size_t)bh * S_ * S_;
    const __nv_bfloat16* Vh = g_vth + (size_t)bh * DK_ * S_;
    const __nv_bfloat16* Vl = g_vtl + (size_t)bh * DK_ * S_;
    float* Aout = attn + (size_t)bh * S_ * S_;

    float acc[2][4][4] = {};
    const int kbase = kz * 512;

    cpA_tile(sb + OFF_AH, sb + OFF_AL, Ph, Pl, S_, m0, kbase, tid);
    cpB_tile(sb + OFF_BH, sb + OFF_BL, Vh, Vl, S_, 0, kbase, tid);
    CP_COMMIT;
    for (int it = 0; it < 8; it++) {
        const int cur = it & 1;
        const unsigned cb = sb + cur * STAGE_BYTES;
        const int k0 = kbase + it * 64;
        if (it + 1 < 8) {
            const unsigned nb = sb + (1 - cur) * STAGE_BYTES;
            cpA_tile(nb + OFF_AH, nb + OFF_AL, Ph, Pl, S_, m0, k0 + 64, tid);
            cpB_tile(nb + OFF_BH, nb + OFF_BL, Vh, Vl, S_, 0, k0 + 64, tid);
            CP_COMMIT;
            CP_WAIT1;
        } else { CP_WAIT0; }
        __syncthreads();

        // write normalized attn fp32 from this stage's A tile (each elem once)
        const char* cbc = sm + cur * STAGE_BYTES;
#pragma unroll
        for (int j = 0; j < 4; j++) {
            int id = tid + j * 256, row = id >> 3, c = id & 7;
            unsigned off = swz(row, c * 16);
            uint4 hv = *reinterpret_cast<const uint4*>(cbc + OFF_AH + off);
            uint4 lv = *reinterpret_cast<const uint4*>(cbc + OFF_AL + off);
            const float inv = s_inv[row];
            float4 o0, o1;
            __nv_bfloat162 h2, l2;
            h2 = *reinterpret_cast<__nv_bfloat162*>(&hv.x);
            l2 = *reinterpret_cast<__nv_bfloat162*>(&lv.x);
            o0.x = (__low2float(h2) + __low2float(l2)) * inv;
            o0.y = (__high2float(h2) + __high2float(l2)) * inv;
            h2 = *reinterpret_cast<__nv_bfloat162*>(&hv.y);
            l2 = *reinterpret_cast<__nv_bfloat162*>(&lv.y);
            o0.z = (__low2float(h2) + __low2float(l2)) * inv;
            o0.w = (__high2float(h2) + __high2float(l2)) * inv;
            h2 = *reinterpret_cast<__nv_bfloat162*>(&hv.z);
            l2 = *reinterpret_cast<__nv_bfloat162*>(&lv.z);
            o1.x = (__low2float(h2) + __low2float(l2)) * inv;
            o1.y = (__high2float(h2) + __high2float(l2)) * inv;
            h2 = *reinterpret_cast<__nv_bfloat162*>(&hv.w);
            l2 = *reinterpret_cast<__nv_bfloat162*>(&lv.w);
            o1.z = (__low2float(h2) + __low2float(l2)) * inv;
            o1.w = (__high2float(h2) + __high2float(l2)) * inv;
            float* dst = Aout + (size_t)(m0 + row) * S_ + k0 + c * 8;
            *reinterpret_cast<float4*>(dst)     = o0;
            *reinterpret_cast<float4*>(dst + 4) = o1;
        }

        compute_stage(cb, wm, wn, lane, acc);
        __syncthreads();
    }

    // epilogue: fp32 partial ctx scaled by inv (linear => valid per partial)
    const int b = bh >> 4, h = bh & 15;
    float* dst = g_ctxp + (size_t)kz * BS_ * D_;
#pragma unroll
    for (int mt = 0; mt < 2; mt++)
#pragma unroll
        for (int nt = 0; nt < 4; nt++) {
            const int c = wn * 32 + nt * 8 + 2 * (lane & 3);
#pragma unroll
            for (int half = 0; half < 2; half++) {
                const int rowl = wm * 32 + mt * 16 + (lane >> 2) + half * 8;
                const float inv = s_inv[rowl];
                const int s = m0 + rowl;
                float2 v = { acc[mt][nt][half * 2] * inv,
                             acc[mt][nt][half * 2 + 1] * inv };
                *reinterpret_cast<float2*>(&dst[(size_t)(b * S_ + s) * D_ + h * DK_ + c]) = v;
            }
        }
}

// ---------------- ctx reduce: sum 4 partials -> hi/lo bf16 ---------------------
__global__ void ctx_reduce()
{
    const size_t i = ((size_t)blockIdx.x * 256 + threadIdx.x) * 2;
    float2 s = {0.f, 0.f};
#pragma unroll
    for (int p = 0; p < 4; p++) {
        float2 v = *reinterpret_cast<const float2*>(&g_ctxp[(size_t)p * BS_ * D_ + i]);
        s.x += v.x; s.y += v.y;
    }
    unsigned hh, ll;
    split2(s.x, s.y, hh, ll);
    *reinterpret_cast<unsigned*>(g_ch + i) = hh;
    *reinterpret_cast<unsigned*>(g_cl + i) = ll;
}

// =============================================================================
// Kernel 4: out = ctx @ Wo^T + bo
// =============================================================================
__global__ __launch_bounds__(256, 2) void oproj_gemm(const float* __restrict__ bo,
                                                     float* __restrict__ out)
{
    extern __shared__ char sm[];
    const unsigned sb = smem_u32(sm);
    const int m0 = blockIdx.y * 128, n0 = blockIdx.x * 64;
    const int tid = threadIdx.x, lane = tid & 31, wid = tid >> 5;
    const int wm = wid >> 1, wn = wid & 1;
    float acc[2][4][4] = {};

    cpA_tile(sb + OFF_AH, sb + OFF_AL, g_ch, g_cl, D_, m0, 0, tid);
    cpB_tile(sb + OFF_BH, sb + OFF_BL, g_woh, g_wol, D_, n0, 0, tid);
    CP_COMMIT;
    for (int it = 0; it < 16; it++) {
        const unsigned cb = sb + (it & 1) * STAGE_BYTES;
        if (it + 1 < 16) {
            const unsigned nb = sb + ((it + 1) & 1) * STAGE_BYTES;
            cpA_tile(nb + OFF_AH, nb + OFF_AL, g_ch, g_cl, D_, m0, (it + 1) * 64, tid);
            cpB_tile(nb + OFF_BH, nb + OFF_BL, g_woh, g_wol, D_, n0, (it + 1) * 64, tid);
            CP_COMMIT;
            CP_WAIT1;
        } else { CP_WAIT0; }
        __syncthreads();
        compute_stage(cb, wm, wn, lane, acc);
        __syncthreads();
    }

    const int tm0 = m0 + wm * 32, tn0 = n0 + wn * 32;
#pragma unroll
    for (int mt = 0; mt < 2; mt++)
#pragma unroll
        for (int nt = 0; nt < 4; nt++) {
            const int c = tn0 + nt * 8 + 2 * (lane & 3);
            const float b0 = bo[c], b1 = bo[c + 1];
#pragma unroll
            for (int half = 0; half < 2; half++) {
                const int m = tm0 + mt * 16 + (lane >> 2) + half * 8;
                float2 v = { acc[mt][nt][half * 2] + b0,
                             acc[mt][nt][half * 2 + 1] + b1 };
                *reinterpret_cast<float2*>(out + (size_t)m * D_ + c) = v;
            }
        }
}

// =============================================================================
extern "C" void kernel_launch(void* const* d_in, const int* in_sizes, int n_in,
                              void* d_out, int out_size)
{
    const float* x  = (const float*)d_in[0];
    const float* wq = (const float*)d_in[1];
    const float* bq = (const float*)d_in[2];
    const float* wk = (const float*)d_in[3];
    const float* bk = (const float*)d_in[4];
    const float* wv = (const float*)d_in[5];
    const float* bv = (const float*)d_in[6];
    const float* wo = (const float*)d_in[7];
    const float* bo = (const float*)d_in[8];

    float* out = (float*)d_out;
    const long long OUT_E  = (long long)BS_ * D_;
    const long long ATTN_E = (long long)NBH_ * S_ * S_;
    float* attn = ((long long)out_size >= OUT_E + ATTN_E) ? (out + OUT_E) : nullptr;

    static bool attr_done = false;
    if (!attr_done) {
        cudaFuncSetAttribute(qkv_gemm,    cudaFuncAttributeMaxDynamicSharedMemorySize, 2 * STAGE_BYTES);
        cudaFuncSetAttribute(pv_gemm,     cudaFuncAttributeMaxDynamicSharedMemorySize, 2 * STAGE_BYTES);
        cudaFuncSetAttribute(oproj_gemm,  cudaFuncAttributeMaxDynamicSharedMemorySize, 2 * STAGE_BYTES);
        cudaFuncSetAttribute(scores_gemm, cudaFuncAttributeMaxDynamicSharedMemorySize, STAGE_BYTES);
        attr_done = true;
    }

    // 0. precision splits
    prep_kernel<<<16384, 256>>>(x, wq, wk, wv, wo);

    // 1. QKV projection (fused N=3072), Q pre-scaled by 1/8
    qkv_gemm<<<dim3(3 * D_ / 64, BS_ / 128), 256, 2 * STAGE_BYTES>>>(bq, bk, bv);

    // 2. P = exp(QK^T/8) bf16 hi/lo + deterministic partial row sums
    scores_gemm<<<dim3(S_ / 64, S_ / 128, NBH_), 256, STAGE_BYTES>>>();

    // 3. inverse row sums
    inv_kernel<<<NBH_ * S_ / 256, 256>>>();

    // 4. pv split-K=4: partial ctx + normalized attn fp32 output
    pv_gemm<<<dim3(4, S_ / 128, NBH_), 256, 2 * STAGE_BYTES>>>(attn);

    // 5. reduce ctx partials -> hi/lo
    ctx_reduce<<<BS_ * D_ / 512, 256>>>();

    // 6. out projection
    oproj_gemm<<<dim3(D_ / 64, BS_ / 128), 256, 2 * STAGE_BYTES>>>(bo, out);
}